// round 6
// baseline (speedup 1.0000x reference)
#include <cuda_runtime.h>
#include <math.h>

// ---------------------------------------------------------------------------
// RadiomicsPreservationLoss — register-rolling stencil with f32x2 packing:
// the (input,output) image pair rides in the (lo,hi) halves of packed
// f32x2 registers; one FFMA2/FADD2/FMUL2 does both images' math per issue.
// occ-3, 444 blocks, rolling 4-row chunks, fused last-block finalize.
// ---------------------------------------------------------------------------

#define HH 512
#define WW 512
#define BB 32
#define NBLK 444                    // 3 blocks per SM on 148 SMs
#define NTHR 256
#define NSLOTS (NBLK * 8)           // 3552 warp slots
#define NCHUNK 16384                // 32 img * 128 row-chunks(4) * 4 strips
#define FULLM 0xffffffffu

__device__ double g_part[NBLK][11];
__device__ unsigned g_cnt = 0;

// ---- packed f32x2 helpers (sm_103a) ----
typedef unsigned long long f2;
__device__ __forceinline__ f2 pk(float lo, float hi) {
    f2 r; asm("mov.b64 %0, {%1, %2};" : "=l"(r) : "f"(lo), "f"(hi)); return r;
}
__device__ __forceinline__ void upk(float& lo, float& hi, f2 v) {
    asm("mov.b64 {%0, %1}, %2;" : "=f"(lo), "=f"(hi) : "l"(v));
}
__device__ __forceinline__ f2 add2(f2 a, f2 b) {
    f2 r; asm("add.rn.f32x2 %0, %1, %2;" : "=l"(r) : "l"(a), "l"(b)); return r;
}
__device__ __forceinline__ f2 mul2(f2 a, f2 b) {
    f2 r; asm("mul.rn.f32x2 %0, %1, %2;" : "=l"(r) : "l"(a), "l"(b)); return r;
}
__device__ __forceinline__ f2 fma2(f2 a, f2 b, f2 c) {
    f2 r; asm("fma.rn.f32x2 %0, %1, %2, %3;" : "=l"(r) : "l"(a), "l"(b), "l"(c)); return r;
}

// Load one row of BOTH images as 6 packed (in,out) values:
// 4 own cols (cb..cb+3) + left halo (cb-1) + right halo (cb+4).
__device__ __forceinline__ void load_row6p(
    f2* __restrict__ R,
    const float* __restrict__ bi, const float* __restrict__ bo,
    int r, int cb, bool hasL, bool hasR, int lane)
{
    const bool ok = ((unsigned)r < (unsigned)HH);
    float4 qi = make_float4(0.f, 0.f, 0.f, 0.f);
    float4 qo = qi;
    if (ok) {
        qi = *(const float4*)(bi + r * WW + cb);
        qo = *(const float4*)(bo + r * WW + cb);
    }
    float ali = __shfl_up_sync(FULLM, qi.w, 1);
    float alo = __shfl_up_sync(FULLM, qo.w, 1);
    float ari = __shfl_down_sync(FULLM, qi.x, 1);
    float aro = __shfl_down_sync(FULLM, qo.x, 1);
    if (lane == 0) {
        ali = (ok && hasL) ? bi[r * WW + cb - 1] : 0.f;
        alo = (ok && hasL) ? bo[r * WW + cb - 1] : 0.f;
    }
    if (lane == 31) {
        ari = (ok && hasR) ? bi[r * WW + cb + 4] : 0.f;
        aro = (ok && hasR) ? bo[r * WW + cb + 4] : 0.f;
    }
    R[0] = pk(qi.x, qo.x);
    R[1] = pk(qi.y, qo.y);
    R[2] = pk(qi.z, qo.z);
    R[3] = pk(qi.w, qo.w);
    R[4] = pk(ali, alo);
    R[5] = pk(ari, aro);
}

// 3x3 variance + laplacian for 4 cols, both images at once (packed).
__device__ __forceinline__ void proc6p(
    const f2* __restrict__ Pp, const f2* __restrict__ Pc,
    const f2* __restrict__ Pn,
    f2* __restrict__ var2, f2* __restrict__ lap2)
{
    f2 cs[6], cq[6];
    #pragma unroll
    for (int j = 0; j < 6; j++) {
        cs[j] = add2(add2(Pp[j], Pc[j]), Pn[j]);
        cq[j] = fma2(Pn[j], Pn[j], fma2(Pc[j], Pc[j], mul2(Pp[j], Pp[j])));
    }
    const f2 i9  = pk( 1.f / 9.f,  1.f / 9.f);
    const f2 ni9 = pk(-1.f / 9.f, -1.f / 9.f);
    const f2 m5  = pk(-5.f, -5.f);
    #pragma unroll
    for (int p = 0; p < 4; p++) {
        f2 csm = (p == 0) ? cs[4] : cs[p - 1];
        f2 csp = (p == 3) ? cs[5] : cs[p + 1];
        f2 cqm = (p == 0) ? cq[4] : cq[p - 1];
        f2 cqp = (p == 3) ? cq[5] : cq[p + 1];
        f2 S = add2(add2(csm, cs[p]), csp);
        f2 Q = add2(add2(cqm, cq[p]), cqp);
        f2 b  = mul2(S, i9);
        f2 nb = mul2(S, ni9);
        var2[p] = fma2(b, nb, mul2(Q, i9));
        f2 am = (p == 0) ? Pc[4] : Pc[p - 1];
        f2 ap = (p == 3) ? Pc[5] : Pc[p + 1];
        lap2[p] = fma2(Pc[p], m5, add2(cs[p], add2(am, ap)));
    }
}

__global__ void __launch_bounds__(NTHR, 3) k_main(
    const float* __restrict__ g_in,
    const float* __restrict__ g_out,
    const float* __restrict__ g_mask,
    float* __restrict__ final_out)
{
    __shared__ float sred[11][8];
    __shared__ bool s_last;
    __shared__ double sacc[11];

    const int t    = threadIdx.x;
    const int lane = t & 31;
    const int wid  = t >> 5;
    const int slot = blockIdx.x * 8 + wid;   // 0..3551

    float msum = 0.f, texs = 0.f, shps = 0.f;
    f2 p1 = 0, p2 = 0, p3 = 0, p4 = 0;       // packed (input, output) moments

    for (int c = slot; c < NCHUNK; c += NSLOTS) {
        const int img   = c >> 9;            // 512 chunks per image
        const int rc    = (c >> 2) & 127;    // 4-row chunk
        const int strip = c & 3;             // 128-col strip
        const int c0    = strip << 7;
        const int cb    = c0 + lane * 4;
        const bool hasL = (strip > 0);
        const bool hasR = (strip < 3);

        const float* bi = g_in   + (size_t)img * HH * WW;
        const float* bo = g_out  + (size_t)img * HH * WW;
        const float* bm = g_mask + (size_t)img * HH * WW;

        const int r0 = rc * 4;

        f2 P[3][6];
        load_row6p(P[0], bi, bo, r0 - 1, cb, hasL, hasR, lane);
        load_row6p(P[1], bi, bo, r0,     cb, hasL, hasR, lane);

        #pragma unroll
        for (int dr = 0; dr < 4; dr++) {
            const int sp = dr % 3, sc = (dr + 1) % 3, sn = (dr + 2) % 3;
            load_row6p(P[sn], bi, bo, r0 + dr + 1, cb, hasL, hasR, lane);

            f2 var2[4], lap2[4];
            proc6p(P[sp], P[sc], P[sn], var2, lap2);

            float4 m0 = *(const float4*)(bm + (r0 + dr) * WW + cb);
            float mv[4] = { m0.x, m0.y, m0.z, m0.w };

            #pragma unroll
            for (int j = 0; j < 4; j++) {
                float m = mv[j];
                msum += m;
                f2 mm  = pk(m, m);
                f2 xy  = P[sc][j];           // (x, y) center pair
                f2 sq  = mul2(xy, xy);
                f2 q   = mul2(sq, mm);
                p1 = fma2(xy, mm, p1);
                p2 = add2(p2, q);
                p3 = fma2(xy, q, p3);
                p4 = fma2(sq, q, p4);
                float vi, vo, li, lo;
                upk(vi, vo, var2[j]);
                upk(li, lo, lap2[j]);
                texs = fmaf(fabsf(vo - vi), m, texs);
                shps = fmaf(fabsf(lo - li), m, shps);
            }
        }
    }

    // ---- unpack packed moments -> 11 scalar partials ----
    float xi1, yo1, xi2, yo2, xi3, yo3, xi4, yo4;
    upk(xi1, yo1, p1);
    upk(xi2, yo2, p2);
    upk(xi3, yo3, p3);
    upk(xi4, yo4, p4);

    float acc[11] = { msum, xi1, xi2, xi3, xi4, yo1, yo2, yo3, yo4, texs, shps };
    #pragma unroll
    for (int k = 0; k < 11; k++) {
        float v = acc[k];
        #pragma unroll
        for (int off = 16; off; off >>= 1)
            v += __shfl_xor_sync(FULLM, v, off);
        if (lane == 0) sred[k][wid] = v;
    }
    __syncthreads();
    if (t < 11) {
        double s = 0.0;
        #pragma unroll
        for (int w = 0; w < 8; w++) s += (double)sred[t][w];
        g_part[blockIdx.x][t] = s;
    }

    // ---- last-block finalize ----
    __threadfence();
    if (t == 0) {
        unsigned prev = atomicAdd(&g_cnt, 1u);
        s_last = (prev == NBLK - 1);
    }
    __syncthreads();
    if (!s_last) return;

    for (int k = wid; k < 11; k += 8) {
        double s = 0.0;
        for (int b = lane; b < NBLK; b += 32)
            s += g_part[b][k];
        #pragma unroll
        for (int off = 16; off; off >>= 1)
            s += __shfl_xor_sync(FULLM, s, off);
        if (lane == 0) sacc[k] = s;
    }
    __syncthreads();

    if (t == 0) {
        g_cnt = 0;   // reset for next graph replay
        const double EPS = 1e-8;
        const double NTOT = (double)BB * HH * WW;

        double M0 = sacc[0];
        double ms = M0 + EPS;
        double Mi1 = sacc[1], Mi2 = sacc[2], Mi3 = sacc[3], Mi4 = sacc[4];
        double Mo1 = sacc[5], Mo2 = sacc[6], Mo3 = sacc[7], Mo4 = sacc[8];

        double im = Mi1 / ms, om = Mo1 / ms;
        double im2 = im * im, om2 = om * om;

        double c2i = Mi2 - 2.0 * im * Mi1 + im2 * M0;
        double c3i = Mi3 - 3.0 * im * Mi2 + 3.0 * im2 * Mi1 - im2 * im * M0;
        double c4i = Mi4 - 4.0 * im * Mi3 + 6.0 * im2 * Mi2 - 4.0 * im2 * im * Mi1 + im2 * im2 * M0;

        double c2o = Mo2 - 2.0 * om * Mo1 + om2 * M0;
        double c3o = Mo3 - 3.0 * om * Mo2 + 3.0 * om2 * Mo1 - om2 * om * M0;
        double c4o = Mo4 - 4.0 * om * Mo3 + 6.0 * om2 * Mo2 - 4.0 * om2 * om * Mo1 + om2 * om2 * M0;

        double iv = c2i / ms, ov = c2o / ms;
        double isk = c3i / (ms * (iv * sqrt(iv) + EPS));
        double osk = c3o / (ms * (ov * sqrt(ov) + EPS));
        double iku = c4i / (ms * (iv * iv + EPS));
        double oku = c4o / (ms * (ov * ov + EPS));

        double dm = im - om, dv = iv - ov, dsk = isk - osk, dku = iku - oku;
        double inten = dm * dm + dv * dv + dsk * dsk + dku * dku;
        double tex = sacc[9]  / NTOT;
        double shp = sacc[10] / NTOT;
        double total = inten + tex + 0.5 * shp;

        final_out[0] = (float)inten;
        final_out[1] = (float)tex;
        final_out[2] = (float)shp;
        final_out[3] = (float)total;
    }
}

extern "C" void kernel_launch(void* const* d_in, const int* in_sizes, int n_in,
                              void* d_out, int out_size) {
    const float* in_img  = (const float*)d_in[0];
    const float* out_img = (const float*)d_in[1];
    const float* mask    = (const float*)d_in[2];

    k_main<<<NBLK, NTHR>>>(in_img, out_img, mask, (float*)d_out);
}

// round 7
// speedup vs baseline: 1.0402x; 1.0402x over previous
#include <cuda_runtime.h>
#include <math.h>

// ---------------------------------------------------------------------------
// RadiomicsPreservationLoss — warp-autonomous stencil (round-4 architecture),
// occupancy 4 (64-reg budget), 592 blocks, 2-row chunks for balance.
// inputs: input_img, output_img, roi_mask  [32,1,512,512] f32
// output: [intensity, texture, shape, total] (4 x f32)
// ---------------------------------------------------------------------------

#define HH 512
#define WW 512
#define BB 32
#define NBLK 592                    // 4 blocks per SM on 148 SMs
#define NTHR 256
#define NSLOTS (NBLK * 8)           // 4736 warp slots
#define NCHUNK 32768                // 32 img * 256 row-chunks(2) * 4 strips
#define FULLM 0xffffffffu

__device__ double g_part[NBLK][11];
__device__ unsigned g_cnt = 0;

__device__ __forceinline__ float4 ld4z(const float* __restrict__ p, bool ok) {
    return ok ? *(const float4*)p : make_float4(0.f, 0.f, 0.f, 0.f);
}

// 3x3 local variance, laplacian, center value for 4 columns per lane.
__device__ __forceinline__ void stencil4(
    const float* __restrict__ base, int r, int cb,
    bool okm, bool okp, bool hasL, bool hasR, int lane,
    float* __restrict__ var, float* __restrict__ lap, float* __restrict__ cen)
{
    const float* p = base + r * WW + cb;
    float a0[4], a1[4], a2[4];
    float4 q;
    q = ld4z(p - WW, okm);   a0[0]=q.x; a0[1]=q.y; a0[2]=q.z; a0[3]=q.w;
    q = *(const float4*)(p); a1[0]=q.x; a1[1]=q.y; a1[2]=q.z; a1[3]=q.w;
    q = ld4z(p + WW, okp);   a2[0]=q.x; a2[1]=q.y; a2[2]=q.z; a2[3]=q.w;

    // strip-edge halo columns (zero at true image boundary), predicated
    float hl0=0.f, hl1=0.f, hl2=0.f, hr0=0.f, hr1=0.f, hr2=0.f;
    if (lane == 0 && hasL) {
        const float* pl = p - 1;
        hl1 = pl[0];
        if (okm) hl0 = pl[-WW];
        if (okp) hl2 = pl[ WW];
    }
    if (lane == 31 && hasR) {
        const float* pr = p + 4;
        hr1 = pr[0];
        if (okm) hr0 = pr[-WW];
        if (okp) hr2 = pr[ WW];
    }

    float cs[4], cq[4];
    #pragma unroll
    for (int j = 0; j < 4; j++) {
        cs[j] = a0[j] + a1[j] + a2[j];
        float u = a0[j] * a0[j];
        u = fmaf(a1[j], a1[j], u);
        cq[j] = fmaf(a2[j], a2[j], u);
    }

    float csL = __shfl_up_sync(FULLM, cs[3], 1);
    float cqL = __shfl_up_sync(FULLM, cq[3], 1);
    float aL  = __shfl_up_sync(FULLM, a1[3], 1);
    if (lane == 0) {
        csL = hl0 + hl1 + hl2;
        float u = hl0 * hl0; u = fmaf(hl1, hl1, u);
        cqL = fmaf(hl2, hl2, u);
        aL  = hl1;
    }
    float csR = __shfl_down_sync(FULLM, cs[0], 1);
    float cqR = __shfl_down_sync(FULLM, cq[0], 1);
    float aR  = __shfl_down_sync(FULLM, a1[0], 1);
    if (lane == 31) {
        csR = hr0 + hr1 + hr2;
        float u = hr0 * hr0; u = fmaf(hr1, hr1, u);
        cqR = fmaf(hr2, hr2, u);
        aR  = hr1;
    }

    const float inv9 = 1.f / 9.f;
    #pragma unroll
    for (int j = 0; j < 4; j++) {
        float cm = (j == 0) ? csL : cs[j - 1];
        float cp = (j == 3) ? csR : cs[j + 1];
        float qm = (j == 0) ? cqL : cq[j - 1];
        float qp = (j == 3) ? cqR : cq[j + 1];
        float S = cm + cs[j] + cp;
        float Q = qm + cq[j] + qp;
        float bmn = S * inv9;
        var[j] = fmaf(-bmn, bmn, Q * inv9);
        float am = (j == 0) ? aL : a1[j - 1];
        float ap = (j == 3) ? aR : a1[j + 1];
        lap[j] = fmaf(-5.f, a1[j], cs[j] + am + ap);
        cen[j] = a1[j];
    }
}

__global__ void __launch_bounds__(NTHR, 4) k_main(
    const float* __restrict__ g_in,
    const float* __restrict__ g_out,
    const float* __restrict__ g_mask,
    float* __restrict__ final_out)
{
    __shared__ float sred[11][8];
    __shared__ bool s_last;
    __shared__ double sacc[11];

    const int t    = threadIdx.x;
    const int lane = t & 31;
    const int wid  = t >> 5;
    const int slot = blockIdx.x * 8 + wid;   // 0..4735

    float msum = 0.f;
    float xi1 = 0.f, xi2 = 0.f, xi3 = 0.f, xi4 = 0.f;
    float yo1 = 0.f, yo2 = 0.f, yo3 = 0.f, yo4 = 0.f;
    float texs = 0.f, shps = 0.f;

    for (int c = slot; c < NCHUNK; c += NSLOTS) {
        const int img   = c >> 10;           // 1024 chunks per image
        const int rc    = (c >> 2) & 255;    // 2-row chunk
        const int strip = c & 3;             // 128-col strip
        const int c0    = strip << 7;
        const int cb    = c0 + lane * 4;
        const bool hasL = (strip > 0);
        const bool hasR = (strip < 3);

        const float* bi = g_in   + (size_t)img * HH * WW;
        const float* bo = g_out  + (size_t)img * HH * WW;
        const float* bm = g_mask + (size_t)img * HH * WW;

        const int r0 = rc * 2;
        #pragma unroll
        for (int dr = 0; dr < 2; dr++) {
            const int r = r0 + dr;
            const bool okm = (r > 0);
            const bool okp = (r < HH - 1);

            // mask load first: joins the independent-load batch
            float4 m0 = *(const float4*)(bm + r * WW + cb);

            float var_i[4], lap_i[4], xc[4];
            stencil4(bi, r, cb, okm, okp, hasL, hasR, lane, var_i, lap_i, xc);
            float var_o[4], lap_o[4], yc[4];
            stencil4(bo, r, cb, okm, okp, hasL, hasR, lane, var_o, lap_o, yc);

            float mv[4] = { m0.x, m0.y, m0.z, m0.w };

            #pragma unroll
            for (int j = 0; j < 4; j++) {
                float m = mv[j];
                msum += m;
                float x = xc[j], y = yc[j];
                float x2 = x * x, y2 = y * y;
                float qx = x2 * m, qy = y2 * m;
                xi1 = fmaf(x, m, xi1);  xi2 += qx;
                xi3 = fmaf(x, qx, xi3); xi4 = fmaf(x2, qx, xi4);
                yo1 = fmaf(y, m, yo1);  yo2 += qy;
                yo3 = fmaf(y, qy, yo3); yo4 = fmaf(y2, qy, yo4);
                texs = fmaf(fabsf(var_o[j] - var_i[j]), m, texs);
                shps = fmaf(fabsf(lap_o[j] - lap_i[j]), m, shps);
            }
        }
    }

    // ---- block reduction -> fp64 partial ----
    float acc[11] = { msum, xi1, xi2, xi3, xi4, yo1, yo2, yo3, yo4, texs, shps };
    #pragma unroll
    for (int k = 0; k < 11; k++) {
        float v = acc[k];
        #pragma unroll
        for (int off = 16; off; off >>= 1)
            v += __shfl_xor_sync(FULLM, v, off);
        if (lane == 0) sred[k][wid] = v;
    }
    __syncthreads();
    if (t < 11) {
        double s = 0.0;
        #pragma unroll
        for (int w = 0; w < 8; w++) s += (double)sred[t][w];
        g_part[blockIdx.x][t] = s;
    }

    // ---- last-block finalize ----
    __threadfence();
    if (t == 0) {
        unsigned prev = atomicAdd(&g_cnt, 1u);
        s_last = (prev == NBLK - 1);
    }
    __syncthreads();
    if (!s_last) return;

    for (int k = wid; k < 11; k += 8) {
        double s = 0.0;
        for (int b = lane; b < NBLK; b += 32)
            s += g_part[b][k];
        #pragma unroll
        for (int off = 16; off; off >>= 1)
            s += __shfl_xor_sync(FULLM, s, off);
        if (lane == 0) sacc[k] = s;
    }
    __syncthreads();

    if (t == 0) {
        g_cnt = 0;   // reset for next graph replay
        const double EPS = 1e-8;
        const double NTOT = (double)BB * HH * WW;

        double M0 = sacc[0];
        double ms = M0 + EPS;
        double Mi1 = sacc[1], Mi2 = sacc[2], Mi3 = sacc[3], Mi4 = sacc[4];
        double Mo1 = sacc[5], Mo2 = sacc[6], Mo3 = sacc[7], Mo4 = sacc[8];

        double im = Mi1 / ms, om = Mo1 / ms;
        double im2 = im * im, om2 = om * om;

        double c2i = Mi2 - 2.0 * im * Mi1 + im2 * M0;
        double c3i = Mi3 - 3.0 * im * Mi2 + 3.0 * im2 * Mi1 - im2 * im * M0;
        double c4i = Mi4 - 4.0 * im * Mi3 + 6.0 * im2 * Mi2 - 4.0 * im2 * im * Mi1 + im2 * im2 * M0;

        double c2o = Mo2 - 2.0 * om * Mo1 + om2 * M0;
        double c3o = Mo3 - 3.0 * om * Mo2 + 3.0 * om2 * Mo1 - om2 * om * M0;
        double c4o = Mo4 - 4.0 * om * Mo3 + 6.0 * om2 * Mo2 - 4.0 * om2 * om * Mo1 + om2 * om2 * M0;

        double iv = c2i / ms, ov = c2o / ms;
        double isk = c3i / (ms * (iv * sqrt(iv) + EPS));
        double osk = c3o / (ms * (ov * sqrt(ov) + EPS));
        double iku = c4i / (ms * (iv * iv + EPS));
        double oku = c4o / (ms * (ov * ov + EPS));

        double dm = im - om, dv = iv - ov, dsk = isk - osk, dku = iku - oku;
        double inten = dm * dm + dv * dv + dsk * dsk + dku * dku;
        double tex = sacc[9]  / NTOT;
        double shp = sacc[10] / NTOT;
        double total = inten + tex + 0.5 * shp;

        final_out[0] = (float)inten;
        final_out[1] = (float)tex;
        final_out[2] = (float)shp;
        final_out[3] = (float)total;
    }
}

extern "C" void kernel_launch(void* const* d_in, const int* in_sizes, int n_in,
                              void* d_out, int out_size) {
    const float* in_img  = (const float*)d_in[0];
    const float* out_img = (const float*)d_in[1];
    const float* mask    = (const float*)d_in[2];

    k_main<<<NBLK, NTHR>>>(in_img, out_img, mask, (float*)d_out);
}

// round 8
// speedup vs baseline: 1.2324x; 1.1848x over previous
#include <cuda_runtime.h>
#include <math.h>

// ---------------------------------------------------------------------------
// RadiomicsPreservationLoss — register-rolling stencil + software pipelining:
// loads for row r+2 (and mask r) issue BEFORE processing row r, so the rolling
// loop's cold loads get ~150 cycles of math to hide under.
// occ-3, 444 blocks, 4-row chunks, fused last-block finalize.
// ---------------------------------------------------------------------------

#define HH 512
#define WW 512
#define BB 32
#define NBLK 444                    // 3 blocks per SM on 148 SMs
#define NTHR 256
#define NSLOTS (NBLK * 8)           // 3552 warp slots
#define NCHUNK 16384                // 32 img * 128 row-chunks(4) * 4 strips
#define FULLM 0xffffffffu

__device__ double g_part[NBLK][11];
__device__ unsigned g_cnt = 0;

// Load one row as 6 values: 4 own cols (cb..cb+3) + left halo (cb-1) + right
// halo (cb+4). Shuffles for interior lane edges, predicated LDG for strip
// edges, zeros outside the image.
__device__ __forceinline__ void load_row6(
    float* __restrict__ R, const float* __restrict__ base,
    int r, int cb, bool hasL, bool hasR, int lane)
{
    const bool ok = ((unsigned)r < (unsigned)HH);
    float4 q = make_float4(0.f, 0.f, 0.f, 0.f);
    if (ok) q = *(const float4*)(base + r * WW + cb);
    R[0] = q.x; R[1] = q.y; R[2] = q.z; R[3] = q.w;

    float al = __shfl_up_sync(FULLM, q.w, 1);     // lane-1's cb+3 == my cb-1
    float ar = __shfl_down_sync(FULLM, q.x, 1);   // lane+1's cb   == my cb+4
    float al_e = (lane == 0  && ok && hasL) ? base[r * WW + cb - 1] : 0.f;
    float ar_e = (lane == 31 && ok && hasR) ? base[r * WW + cb + 4] : 0.f;
    R[4] = (lane == 0)  ? al_e : al;
    R[5] = (lane == 31) ? ar_e : ar;
}

// 3x3 variance, laplacian, center for 4 cols from three rolled 6-wide rows.
__device__ __forceinline__ void proc6(
    const float* __restrict__ Ap, const float* __restrict__ Ac,
    const float* __restrict__ An,
    float* __restrict__ var, float* __restrict__ lap, float* __restrict__ cen)
{
    float cs[6], cq[6];
    #pragma unroll
    for (int j = 0; j < 6; j++) {
        cs[j] = Ap[j] + Ac[j] + An[j];
        float u = Ap[j] * Ap[j];
        u = fmaf(Ac[j], Ac[j], u);
        cq[j] = fmaf(An[j], An[j], u);
    }
    const float inv9 = 1.f / 9.f;
    #pragma unroll
    for (int p = 0; p < 4; p++) {
        float Sm = (p == 0) ? cs[4] : cs[p - 1];
        float Sp = (p == 3) ? cs[5] : cs[p + 1];
        float Qm = (p == 0) ? cq[4] : cq[p - 1];
        float Qp = (p == 3) ? cq[5] : cq[p + 1];
        float S = Sm + cs[p] + Sp;
        float Q = Qm + cq[p] + Qp;
        float bmn = S * inv9;
        var[p] = fmaf(-bmn, bmn, Q * inv9);
        float am = (p == 0) ? Ac[4] : Ac[p - 1];
        float ap = (p == 3) ? Ac[5] : Ac[p + 1];
        lap[p] = fmaf(-5.f, Ac[p], cs[p] + am + ap);
        cen[p] = Ac[p];
    }
}

__global__ void __launch_bounds__(NTHR, 3) k_main(
    const float* __restrict__ g_in,
    const float* __restrict__ g_out,
    const float* __restrict__ g_mask,
    float* __restrict__ final_out)
{
    __shared__ float sred[11][8];
    __shared__ bool s_last;
    __shared__ double sacc[11];

    const int t    = threadIdx.x;
    const int lane = t & 31;
    const int wid  = t >> 5;
    const int slot = blockIdx.x * 8 + wid;   // 0..3551

    float msum = 0.f;
    float xi1 = 0.f, xi2 = 0.f, xi3 = 0.f, xi4 = 0.f;
    float yo1 = 0.f, yo2 = 0.f, yo3 = 0.f, yo4 = 0.f;
    float texs = 0.f, shps = 0.f;

    for (int c = slot; c < NCHUNK; c += NSLOTS) {
        const int img   = c >> 9;            // 512 chunks per image
        const int rc    = (c >> 2) & 127;    // 4-row chunk
        const int strip = c & 3;             // 128-col strip
        const int c0    = strip << 7;
        const int cb    = c0 + lane * 4;
        const bool hasL = (strip > 0);
        const bool hasR = (strip < 3);

        const float* bi = g_in   + (size_t)img * HH * WW;
        const float* bo = g_out  + (size_t)img * HH * WW;
        const float* bm = g_mask + (size_t)img * HH * WW;

        const int r0 = rc * 4;

        // prime the 3-row window (6 independent loads in flight)
        float Pi[3][6], Po[3][6];
        load_row6(Pi[0], bi, r0 - 1, cb, hasL, hasR, lane);
        load_row6(Po[0], bo, r0 - 1, cb, hasL, hasR, lane);
        load_row6(Pi[1], bi, r0,     cb, hasL, hasR, lane);
        load_row6(Po[1], bo, r0,     cb, hasL, hasR, lane);
        load_row6(Pi[2], bi, r0 + 1, cb, hasL, hasR, lane);
        load_row6(Po[2], bo, r0 + 1, cb, hasL, hasR, lane);

        #pragma unroll
        for (int dr = 0; dr < 4; dr++) {
            const int sp = dr % 3, sc = (dr + 1) % 3, sn = (dr + 2) % 3;

            // ---- prefetch: issue loads for row r0+dr+2 and mask row r0+dr
            //      BEFORE any math that consumes resident state ----
            float Fi[6], Fo[6];
            if (dr < 3) {
                load_row6(Fi, bi, r0 + dr + 2, cb, hasL, hasR, lane);
                load_row6(Fo, bo, r0 + dr + 2, cb, hasL, hasR, lane);
            }
            float4 m0 = *(const float4*)(bm + (r0 + dr) * WW + cb);

            // ---- process output row r0+dr from resident registers ----
            float vi[4], li[4], xc[4];
            proc6(Pi[sp], Pi[sc], Pi[sn], vi, li, xc);
            float vo[4], lo[4], yc[4];
            proc6(Po[sp], Po[sc], Po[sn], vo, lo, yc);

            float mv[4] = { m0.x, m0.y, m0.z, m0.w };
            #pragma unroll
            for (int j = 0; j < 4; j++) {
                float m = mv[j];
                msum += m;
                float x = xc[j], y = yc[j];
                float x2 = x * x, y2 = y * y;
                float qx = x2 * m, qy = y2 * m;
                xi1 = fmaf(x, m, xi1);  xi2 += qx;
                xi3 = fmaf(x, qx, xi3); xi4 = fmaf(x2, qx, xi4);
                yo1 = fmaf(y, m, yo1);  yo2 += qy;
                yo3 = fmaf(y, qy, yo3); yo4 = fmaf(y2, qy, yo4);
                texs = fmaf(fabsf(vo[j] - vi[j]), m, texs);
                shps = fmaf(fabsf(lo[j] - li[j]), m, shps);
            }

            // ---- retire in-flight row into the freed ring slot ----
            if (dr < 3) {
                #pragma unroll
                for (int j = 0; j < 6; j++) { Pi[sp][j] = Fi[j]; Po[sp][j] = Fo[j]; }
            }
        }
    }

    // ---- block reduction -> fp64 partial ----
    float acc[11] = { msum, xi1, xi2, xi3, xi4, yo1, yo2, yo3, yo4, texs, shps };
    #pragma unroll
    for (int k = 0; k < 11; k++) {
        float v = acc[k];
        #pragma unroll
        for (int off = 16; off; off >>= 1)
            v += __shfl_xor_sync(FULLM, v, off);
        if (lane == 0) sred[k][wid] = v;
    }
    __syncthreads();
    if (t < 11) {
        double s = 0.0;
        #pragma unroll
        for (int w = 0; w < 8; w++) s += (double)sred[t][w];
        g_part[blockIdx.x][t] = s;
    }

    // ---- last-block finalize ----
    __threadfence();
    if (t == 0) {
        unsigned prev = atomicAdd(&g_cnt, 1u);
        s_last = (prev == NBLK - 1);
    }
    __syncthreads();
    if (!s_last) return;

    for (int k = wid; k < 11; k += 8) {
        double s = 0.0;
        for (int b = lane; b < NBLK; b += 32)
            s += g_part[b][k];
        #pragma unroll
        for (int off = 16; off; off >>= 1)
            s += __shfl_xor_sync(FULLM, s, off);
        if (lane == 0) sacc[k] = s;
    }
    __syncthreads();

    if (t == 0) {
        g_cnt = 0;   // reset for next graph replay
        const double EPS = 1e-8;
        const double NTOT = (double)BB * HH * WW;

        double M0 = sacc[0];
        double ms = M0 + EPS;
        double Mi1 = sacc[1], Mi2 = sacc[2], Mi3 = sacc[3], Mi4 = sacc[4];
        double Mo1 = sacc[5], Mo2 = sacc[6], Mo3 = sacc[7], Mo4 = sacc[8];

        double im = Mi1 / ms, om = Mo1 / ms;
        double im2 = im * im, om2 = om * om;

        double c2i = Mi2 - 2.0 * im * Mi1 + im2 * M0;
        double c3i = Mi3 - 3.0 * im * Mi2 + 3.0 * im2 * Mi1 - im2 * im * M0;
        double c4i = Mi4 - 4.0 * im * Mi3 + 6.0 * im2 * Mi2 - 4.0 * im2 * im * Mi1 + im2 * im2 * M0;

        double c2o = Mo2 - 2.0 * om * Mo1 + om2 * M0;
        double c3o = Mo3 - 3.0 * om * Mo2 + 3.0 * om2 * Mo1 - om2 * om * M0;
        double c4o = Mo4 - 4.0 * om * Mo3 + 6.0 * om2 * Mo2 - 4.0 * om2 * om * Mo1 + om2 * om2 * M0;

        double iv = c2i / ms, ov = c2o / ms;
        double isk = c3i / (ms * (iv * sqrt(iv) + EPS));
        double osk = c3o / (ms * (ov * sqrt(ov) + EPS));
        double iku = c4i / (ms * (iv * iv + EPS));
        double oku = c4o / (ms * (ov * ov + EPS));

        double dm = im - om, dv = iv - ov, dsk = isk - osk, dku = iku - oku;
        double inten = dm * dm + dv * dv + dsk * dsk + dku * dku;
        double tex = sacc[9]  / NTOT;
        double shp = sacc[10] / NTOT;
        double total = inten + tex + 0.5 * shp;

        final_out[0] = (float)inten;
        final_out[1] = (float)tex;
        final_out[2] = (float)shp;
        final_out[3] = (float)total;
    }
}

extern "C" void kernel_launch(void* const* d_in, const int* in_sizes, int n_in,
                              void* d_out, int out_size) {
    const float* in_img  = (const float*)d_in[0];
    const float* out_img = (const float*)d_in[1];
    const float* mask    = (const float*)d_in[2];

    k_main<<<NBLK, NTHR>>>(in_img, out_img, mask, (float*)d_out);
}